// round 7
// baseline (speedup 1.0000x reference)
#include <cuda_runtime.h>
#include <cuda_fp16.h>
#include <cstdint>
#include <math.h>

// ---------------------------------------------------------------------------
// Problem constants
// ---------------------------------------------------------------------------
#define BATCH  32
#define SEQ    480
#define DIMN   1024
#define HEADS  16
#define HD     64
#define MROWS  (BATCH * SEQ)        // 15360
#define PLD    3072                 // fused QKV projection row stride
#define ATTN_SCALE 0.125f

// ---------------------------------------------------------------------------
// Device scratch (allocation-free)
// ---------------------------------------------------------------------------
__device__ __half g_QKVhi[(size_t)MROWS * PLD];
__device__ __half g_QKVlo[(size_t)MROWS * PLD];   // only V columns ever written/read
__device__ __half g_qhi[(size_t)MROWS * DIMN];
__device__ __half g_Ohi[(size_t)MROWS * DIMN];
__device__ __half g_Wcat_hi[(size_t)PLD * DIMN];  // [Wq;Wk;Wv]
__device__ __half g_Wcat_lo[(size_t)PLD * DIMN];  // only Wv part read
__device__ __half g_Wo_hi[(size_t)DIMN * DIMN];
__device__ __half g_Wo_lo[(size_t)DIMN * DIMN];

// ---------------------------------------------------------------------------
// PTX helpers (sm_80-era, arch-portable: mma.sync / ldmatrix / cp.async)
// ---------------------------------------------------------------------------
__device__ __forceinline__ uint32_t smem_to_u32(const void* p) {
    uint32_t a;
    asm("{ .reg .u64 t; cvta.to.shared.u64 t, %1; cvt.u32.u64 %0, t; }"
        : "=r"(a) : "l"(p));
    return a;
}

__device__ __forceinline__ void mma16816(float* d, const uint32_t* a,
                                         const uint32_t* b) {
    asm volatile(
        "mma.sync.aligned.m16n8k16.row.col.f32.f16.f16.f32 "
        "{%0,%1,%2,%3}, {%4,%5,%6,%7}, {%8,%9}, {%0,%1,%2,%3};"
        : "+f"(d[0]), "+f"(d[1]), "+f"(d[2]), "+f"(d[3])
        : "r"(a[0]), "r"(a[1]), "r"(a[2]), "r"(a[3]),
          "r"(b[0]), "r"(b[1]));
}

__device__ __forceinline__ void ldsm_x4(uint32_t* r, uint32_t saddr) {
    asm volatile(
        "ldmatrix.sync.aligned.m8n8.x4.shared.b16 {%0,%1,%2,%3}, [%4];"
        : "=r"(r[0]), "=r"(r[1]), "=r"(r[2]), "=r"(r[3]) : "r"(saddr));
}

__device__ __forceinline__ void ldsm_x4_t(uint32_t* r, uint32_t saddr) {
    asm volatile(
        "ldmatrix.sync.aligned.m8n8.x4.trans.shared.b16 {%0,%1,%2,%3}, [%4];"
        : "=r"(r[0]), "=r"(r[1]), "=r"(r[2]), "=r"(r[3]) : "r"(saddr));
}

__device__ __forceinline__ void cp16(uint32_t s, const void* g) {
    asm volatile("cp.async.cg.shared.global [%0], [%1], 16;"
                 :: "r"(s), "l"(g));
}
#define CP_COMMIT() asm volatile("cp.async.commit_group;" ::: "memory")
#define CP_WAIT2()  asm volatile("cp.async.wait_group 2;"  ::: "memory")
#define CP_WAIT1()  asm volatile("cp.async.wait_group 1;"  ::: "memory")
#define CP_WAIT0()  asm volatile("cp.async.wait_group 0;"  ::: "memory")

__device__ __forceinline__ uint32_t pack_h2(float a, float b) {
    __half2 h = __half2{__float2half_rn(a), __float2half_rn(b)};
    return *(uint32_t*)&h;
}

// ---------------------------------------------------------------------------
// fp32 -> fp16 hi/lo split, and hi-only convert (float4 per thread)
// ---------------------------------------------------------------------------
__global__ __launch_bounds__(256)
void split_kernel(const float* __restrict__ x,
                  __half* __restrict__ hi,
                  __half* __restrict__ lo, int n)
{
    int i = (blockIdx.x * 256 + threadIdx.x) * 4;
    if (i >= n) return;
    float4 v = *(const float4*)(x + i);
    float vv[4] = {v.x, v.y, v.z, v.w};
    __half h[4], l[4];
#pragma unroll
    for (int j = 0; j < 4; j++) {
        h[j] = __float2half_rn(vv[j]);
        l[j] = __float2half_rn(vv[j] - __half2float(h[j]));
    }
    __half2* hp = (__half2*)(hi + i);
    __half2* lp = (__half2*)(lo + i);
    hp[0] = __half2{h[0], h[1]};
    hp[1] = __half2{h[2], h[3]};
    lp[0] = __half2{l[0], l[1]};
    lp[1] = __half2{l[2], l[3]};
}

__global__ __launch_bounds__(256)
void tohalf_kernel(const float* __restrict__ x,
                   __half* __restrict__ hi, int n)
{
    int i = (blockIdx.x * 256 + threadIdx.x) * 4;
    if (i >= n) return;
    float4 v = *(const float4*)(x + i);
    __half2* hp = (__half2*)(hi + i);
    hp[0] = __half2{__float2half_rn(v.x), __float2half_rn(v.y)};
    hp[1] = __half2{__float2half_rn(v.z), __float2half_rn(v.w)};
}

// ---------------------------------------------------------------------------
// fp16 tensor-core GEMM: C = Ah @ Bh^T  (+ Ah @ Bl^T for CTAs with n0>=n_x2)
// HOUT=false: fp32 out (+bias).  HOUT=true: fp16 hi out; lo out only for
// columns >= lo_min.
// CTA tile 128x128, BK=32, 3-stage cp.async pipeline, 256 thr, 2 CTAs/SM.
// ---------------------------------------------------------------------------
#define ASTR   80
#define TILE_B (128 * ASTR)              // 10240
#define OFF_AH 0
#define OFF_BH (1 * TILE_B)
#define OFF_BL (2 * TILE_B)
#define BUF_B  (3 * TILE_B)              // 30720 per stage
#define GEMM_SMEM (3 * BUF_B)            // 92160

template <bool BIAS, bool HOUT>
__global__ __launch_bounds__(256, 2)
void gemm_f16x2(const __half* __restrict__ Ahi,
                const __half* __restrict__ Bhi,
                const __half* __restrict__ Blo,
                const float* __restrict__ bias,
                float* __restrict__ C,
                __half* __restrict__ Chi,
                __half* __restrict__ Clo, int ldc, int lo_min, int n_x2)
{
    extern __shared__ __align__(128) char smem[];
    const uint32_t sb = smem_to_u32(smem);

    const int tid  = threadIdx.x;
    const int lane = tid & 31;
    const int wid  = tid >> 5;
    const int wm   = wid >> 1;
    const int wn   = wid & 1;
    const int m0   = blockIdx.y * 128;
    const int n0   = blockIdx.x * 128;
    const bool do2 = (n0 >= n_x2);

    const int lrow0 = tid >> 2;
    const int lch   = (tid & 3) * 8;

    const __half* gAh = Ahi + (size_t)(m0 + lrow0) * DIMN + lch;
    const __half* gBh = Bhi + (size_t)(n0 + lrow0) * DIMN + lch;
    const __half* gBl = Blo + (size_t)(n0 + lrow0) * DIMN + lch;
    const size_t rstep = (size_t)64 * DIMN;
    const uint32_t s0 = (uint32_t)(lrow0 * ASTR + (tid & 3) * 16);
    const uint32_t s1 = s0 + (uint32_t)(64 * ASTR);

    const uint32_t aByte = (uint32_t)((wm * 32 + (lane & 15)) * ASTR +
                                      (lane >> 4) * 16);
    const uint32_t bByte = (uint32_t)((wn * 64 + ((lane >> 4) << 3) + (lane & 7)) * ASTR +
                                      ((lane >> 3) & 1) * 16);

    float acc[2][8][4];
#pragma unroll
    for (int i = 0; i < 2; i++)
#pragma unroll
        for (int j = 0; j < 8; j++)
#pragma unroll
            for (int c = 0; c < 4; c++) acc[i][j][c] = 0.f;

#pragma unroll
    for (int st = 0; st < 3; st++) {
        const int k0 = st * 32;
        const uint32_t base = sb + st * BUF_B;
        cp16(base + OFF_AH + s0, gAh + k0);
        cp16(base + OFF_AH + s1, gAh + k0 + rstep);
        cp16(base + OFF_BH + s0, gBh + k0);
        cp16(base + OFF_BH + s1, gBh + k0 + rstep);
        if (do2) {
            cp16(base + OFF_BL + s0, gBl + k0);
            cp16(base + OFF_BL + s1, gBl + k0 + rstep);
        }
        CP_COMMIT();
    }

    for (int s = 0; s < 32; s++) {
        CP_WAIT2();
        __syncthreads();

        const uint32_t base = sb + (s % 3) * BUF_B;

#pragma unroll
        for (int kk = 0; kk < 2; kk++) {
            uint32_t ah[2][4];
#pragma unroll
            for (int mi = 0; mi < 2; mi++)
                ldsm_x4(ah[mi], base + OFF_AH + aByte + mi * 16 * ASTR + kk * 32);
            uint32_t bh[4][4], bl[4][4];
#pragma unroll
            for (int bn = 0; bn < 4; bn++)
                ldsm_x4(bh[bn], base + OFF_BH + bByte + bn * 16 * ASTR + kk * 32);
            if (do2) {
#pragma unroll
                for (int bn = 0; bn < 4; bn++)
                    ldsm_x4(bl[bn], base + OFF_BL + bByte + bn * 16 * ASTR + kk * 32);
            }
#pragma unroll
            for (int mi = 0; mi < 2; mi++)
#pragma unroll
                for (int ni = 0; ni < 8; ni++) {
                    const uint32_t* fh = &bh[ni >> 1][(ni & 1) * 2];
                    mma16816(acc[mi][ni], ah[mi], fh);
                    if (do2) {
                        const uint32_t* fl = &bl[ni >> 1][(ni & 1) * 2];
                        mma16816(acc[mi][ni], ah[mi], fl);
                    }
                }
        }

        __syncthreads();
        if (s + 3 < 32) {
            const int k0 = (s + 3) * 32;
            const uint32_t nb = sb + (s % 3) * BUF_B;
            cp16(nb + OFF_AH + s0, gAh + k0);
            cp16(nb + OFF_AH + s1, gAh + k0 + rstep);
            cp16(nb + OFF_BH + s0, gBh + k0);
            cp16(nb + OFF_BH + s1, gBh + k0 + rstep);
            if (do2) {
                cp16(nb + OFF_BL + s0, gBl + k0);
                cp16(nb + OFF_BL + s1, gBl + k0 + rstep);
            }
        }
        CP_COMMIT();
    }

    const bool wlo = HOUT && (n0 >= lo_min);
#pragma unroll
    for (int mi = 0; mi < 2; mi++) {
        const int row = m0 + wm * 32 + mi * 16 + (lane >> 2);
#pragma unroll
        for (int ni = 0; ni < 8; ni++) {
            const int col = n0 + wn * 64 + ni * 8 + ((lane & 3) << 1);
            if (HOUT) {
                float v00 = acc[mi][ni][0], v01 = acc[mi][ni][1];
                float v10 = acc[mi][ni][2], v11 = acc[mi][ni][3];
                __half h00 = __float2half_rn(v00), h01 = __float2half_rn(v01);
                __half h10 = __float2half_rn(v10), h11 = __float2half_rn(v11);
                *(__half2*)(Chi + (size_t)row * ldc + col)       = __half2{h00, h01};
                *(__half2*)(Chi + (size_t)(row + 8) * ldc + col) = __half2{h10, h11};
                if (wlo) {
                    __half l00 = __float2half_rn(v00 - __half2float(h00));
                    __half l01 = __float2half_rn(v01 - __half2float(h01));
                    __half l10 = __float2half_rn(v10 - __half2float(h10));
                    __half l11 = __float2half_rn(v11 - __half2float(h11));
                    *(__half2*)(Clo + (size_t)row * ldc + col)       = __half2{l00, l01};
                    *(__half2*)(Clo + (size_t)(row + 8) * ldc + col) = __half2{l10, l11};
                }
            } else {
                float b0 = 0.f, b1 = 0.f;
                if (BIAS) { b0 = bias[col]; b1 = bias[col + 1]; }
                float2 v0 = make_float2(acc[mi][ni][0] + b0, acc[mi][ni][1] + b1);
                float2 v1 = make_float2(acc[mi][ni][2] + b0, acc[mi][ni][3] + b1);
                *(float2*)(C + (size_t)row * ldc + col)       = v0;
                *(float2*)(C + (size_t)(row + 8) * ldc + col) = v1;
            }
        }
    }
}

// ---------------------------------------------------------------------------
// Tensor-core flash attention.
// CTA: 192 threads (6 warps x 16 q-rows = 96 rows). grid (5, B*H).
// K/V in 64-key blocks, cp.async double buffer.
// S = Qh*Kh (x1);  O = Ph*(Vh+Vl) (x2).  Output: fp16 hi only.
// ---------------------------------------------------------------------------
#define QROWS 96
#define ATHREADS 192
#define KSTR 144                         // bytes per 64-half row (128+16)
#define KV_PLANE (64 * KSTR)             // 9216
#define KV_STAGE (3 * KV_PLANE)          // 27648  (Khi,Vhi,Vlo)
#define Q_OFF (2 * KV_STAGE)             // 55296
#define Q_PLANE (QROWS * KSTR)           // 13824
#define ATTN_SMEM (Q_OFF + Q_PLANE)      // 69120

__global__ __launch_bounds__(ATHREADS, 2)
void attn_mma_kernel(const float* __restrict__ pe,
                     const __half* __restrict__ QKVhi,
                     const __half* __restrict__ QKVlo,
                     __half* __restrict__ Ohi)
{
    extern __shared__ __align__(128) char smem[];
    const uint32_t sb = smem_to_u32(smem);
    const int tid  = threadIdx.x;
    const int lane = tid & 31;
    const int wid  = tid >> 5;
    const int q0   = blockIdx.x * QROWS;
    const int bh   = blockIdx.y;
    const int b    = bh >> 4;
    const int h    = bh & 15;

    const size_t rowbase = (size_t)b * SEQ;

    // ---- Q load (hi plane only; part of group 0) ----
    {
        const size_t gq = (rowbase + q0) * PLD + h * HD;
        for (int c = tid; c < QROWS * 8; c += ATHREADS) {
            const int row = c >> 3, ch = c & 7;
            cp16(sb + Q_OFF + (uint32_t)(row * KSTR + ch * 16),
                 QKVhi + gq + (size_t)row * PLD + ch * 8);
        }
    }

    // ---- K/V stage loader: 3 planes (Khi, Vhi, Vlo) ----
    auto load_kv = [&](int kb, int st) {
        const int k0 = kb * 64;
        for (int c = tid; c < 1536; c += ATHREADS) {
            const int plane = c >> 9;           // 0 Khi 1 Vhi 2 Vlo
            const int idx = c & 511;
            const int row = idx >> 3, ch = idx & 7;
            int kr = k0 + row;
            if (kr >= SEQ) kr = SEQ - 1;        // clamp; masked via S later
            const __half* base = (plane == 2) ? QKVlo : QKVhi;
            const int coloff = (plane == 0) ? DIMN : 2 * DIMN;
            const __half* src = base + (rowbase + kr) * PLD + coloff + h * HD + ch * 8;
            cp16(sb + st * KV_STAGE + plane * KV_PLANE + (uint32_t)(row * KSTR + ch * 16), src);
        }
        CP_COMMIT();
    };

    load_kv(0, 0);     // group 0 (Q + kv0)
    load_kv(1, 1);     // group 1

    // fragment addressing
    const uint32_t qrow_byte = (uint32_t)((wid * 16 + (lane & 15)) * KSTR + (lane >> 4) * 16);
    const uint32_t krow_byte = (uint32_t)((((lane >> 4) << 3) + (lane & 7)) * KSTR +
                                          ((lane >> 3) & 1) * 16);
    const uint32_t vrow_byte = (uint32_t)((lane & 15) * KSTR + (lane >> 4) * 16);

    const int r0  = lane >> 2;
    const int c2  = (lane & 3) * 2;
    const int qr  = q0 + wid * 16 + r0;        // global q row (always < SEQ)
    const float* peA = pe + (size_t)qr * SEQ;
    const float* peB = pe + (size_t)(qr + 8) * SEQ;

    float o[8][4];
#pragma unroll
    for (int i = 0; i < 8; i++)
#pragma unroll
        for (int c = 0; c < 4; c++) o[i][c] = 0.f;
    float mrow0 = -INFINITY, mrow1 = -INFINITY;
    float lsum0 = 0.f, lsum1 = 0.f;

    for (int kb = 0; kb < 8; kb++) {
        if (kb < 7) { CP_WAIT1(); } else { CP_WAIT0(); }
        __syncthreads();

        const uint32_t kvbase = sb + (uint32_t)((kb & 1) * KV_STAGE);
        const int k0 = kb * 64;

        // ---- S = Qh @ Kh^T ----
        float s[8][4];
#pragma unroll
        for (int i = 0; i < 8; i++)
#pragma unroll
            for (int c = 0; c < 4; c++) s[i][c] = 0.f;

#pragma unroll
        for (int ks = 0; ks < 4; ks++) {
            uint32_t qh[4];
            ldsm_x4(qh, sb + Q_OFF + qrow_byte + ks * 32);
            uint32_t kh[4][4];
#pragma unroll
            for (int ng = 0; ng < 4; ng++)
                ldsm_x4(kh[ng], kvbase + 0 * KV_PLANE + krow_byte + ng * 16 * KSTR + ks * 32);
#pragma unroll
            for (int ni = 0; ni < 8; ni++)
                mma16816(s[ni], qh, &kh[ni >> 1][(ni & 1) * 2]);
        }

        // ---- scale + pe bias + mask ----
#pragma unroll
        for (int ni = 0; ni < 8; ni++) {
            const int kc = k0 + ni * 8 + c2;
            if (kc < SEQ) {
                float2 pA = *(const float2*)(peA + kc);
                float2 pB = *(const float2*)(peB + kc);
                s[ni][0] = s[ni][0] * ATTN_SCALE + pA.x;
                s[ni][1] = s[ni][1] * ATTN_SCALE + pA.y;
                s[ni][2] = s[ni][2] * ATTN_SCALE + pB.x;
                s[ni][3] = s[ni][3] * ATTN_SCALE + pB.y;
            } else {
                s[ni][0] = -1e30f; s[ni][1] = -1e30f;
                s[ni][2] = -1e30f; s[ni][3] = -1e30f;
            }
        }

        // ---- online softmax ----
        float m0 = -INFINITY, m1 = -INFINITY;
#pragma unroll
        for (int ni = 0; ni < 8; ni++) {
            m0 = fmaxf(m0, fmaxf(s[ni][0], s[ni][1]));
            m1 = fmaxf(m1, fmaxf(s[ni][2], s[ni][3]));
        }
        m0 = fmaxf(m0, __shfl_xor_sync(0xffffffffu, m0, 1));
        m0 = fmaxf(m0, __shfl_xor_sync(0xffffffffu, m0, 2));
        m1 = fmaxf(m1, __shfl_xor_sync(0xffffffffu, m1, 1));
        m1 = fmaxf(m1, __shfl_xor_sync(0xffffffffu, m1, 2));

        const float mn0 = fmaxf(mrow0, m0);
        const float mn1 = fmaxf(mrow1, m1);
        const float f0 = __expf(mrow0 - mn0);
        const float f1 = __expf(mrow1 - mn1);
        mrow0 = mn0; mrow1 = mn1;

        float sum0 = 0.f, sum1 = 0.f;
        uint32_t phi[4][4];
#pragma unroll
        for (int ks = 0; ks < 4; ks++) {
            const int n0i = 2 * ks, n1i = 2 * ks + 1;
            float p00 = __expf(s[n0i][0] - mn0), p01 = __expf(s[n0i][1] - mn0);
            float p02 = __expf(s[n0i][2] - mn1), p03 = __expf(s[n0i][3] - mn1);
            float p10 = __expf(s[n1i][0] - mn0), p11 = __expf(s[n1i][1] - mn0);
            float p12 = __expf(s[n1i][2] - mn1), p13 = __expf(s[n1i][3] - mn1);
            sum0 += p00 + p01 + p10 + p11;
            sum1 += p02 + p03 + p12 + p13;
            phi[ks][0] = pack_h2(p00, p01);
            phi[ks][1] = pack_h2(p02, p03);
            phi[ks][2] = pack_h2(p10, p11);
            phi[ks][3] = pack_h2(p12, p13);
        }
        lsum0 = lsum0 * f0 + sum0;     // cross-lane reduce deferred to end
        lsum1 = lsum1 * f1 + sum1;

#pragma unroll
        for (int ni = 0; ni < 8; ni++) {
            o[ni][0] *= f0; o[ni][1] *= f0;
            o[ni][2] *= f1; o[ni][3] *= f1;
        }

        // ---- O += Ph @ (Vh + Vl) ----
#pragma unroll
        for (int ks = 0; ks < 4; ks++) {
            uint32_t vh[4][4], vl[4][4];
#pragma unroll
            for (int dg = 0; dg < 4; dg++) {
                ldsm_x4_t(vh[dg], kvbase + 1 * KV_PLANE + vrow_byte + ks * 16 * KSTR + dg * 32);
                ldsm_x4_t(vl[dg], kvbase + 2 * KV_PLANE + vrow_byte + ks * 16 * KSTR + dg * 32);
            }
#pragma unroll
            for (int ni = 0; ni < 8; ni++) {
                const uint32_t* fh = &vh[ni >> 1][(ni & 1) * 2];
                const uint32_t* fl = &vl[ni >> 1][(ni & 1) * 2];
                mma16816(o[ni], phi[ks], fh);
                mma16816(o[ni], phi[ks], fl);
            }
        }

        __syncthreads();
        if (kb + 2 < 8) load_kv(kb + 2, kb & 1);
    }

    // ---- finalize: reduce lsum across the 4 lanes of each row ----
    lsum0 += __shfl_xor_sync(0xffffffffu, lsum0, 1);
    lsum0 += __shfl_xor_sync(0xffffffffu, lsum0, 2);
    lsum1 += __shfl_xor_sync(0xffffffffu, lsum1, 1);
    lsum1 += __shfl_xor_sync(0xffffffffu, lsum1, 2);
    const float inv0 = 1.f / lsum0;
    const float inv1 = 1.f / lsum1;

    const size_t orow0 = (rowbase + qr) * DIMN + h * HD;
    const size_t orow1 = (rowbase + qr + 8) * DIMN + h * HD;
#pragma unroll
    for (int ni = 0; ni < 8; ni++) {
        const int d = ni * 8 + c2;
        *(__half2*)(Ohi + orow0 + d) =
            __half2{__float2half_rn(o[ni][0] * inv0), __float2half_rn(o[ni][1] * inv0)};
        *(__half2*)(Ohi + orow1 + d) =
            __half2{__float2half_rn(o[ni][2] * inv1), __float2half_rn(o[ni][3] * inv1)};
    }
}

// ---------------------------------------------------------------------------
extern "C" void kernel_launch(void* const* d_in, const int* in_sizes, int n_in,
                              void* d_out, int out_size)
{
    const float* q  = (const float*)d_in[0];
    const float* Wq = (const float*)d_in[1];
    const float* Wk = (const float*)d_in[2];
    const float* Wv = (const float*)d_in[3];
    const float* pe = (const float*)d_in[4];
    const float* Wo = (const float*)d_in[5];
    const float* bo = (const float*)d_in[6];
    float* out = (float*)d_out;

    __half *QKVhi, *QKVlo, *qhi, *Ohi, *Wch, *Wcl, *Woh, *Wol;
    cudaGetSymbolAddress((void**)&QKVhi, g_QKVhi);
    cudaGetSymbolAddress((void**)&QKVlo, g_QKVlo);
    cudaGetSymbolAddress((void**)&qhi, g_qhi);
    cudaGetSymbolAddress((void**)&Ohi, g_Ohi);
    cudaGetSymbolAddress((void**)&Wch, g_Wcat_hi);
    cudaGetSymbolAddress((void**)&Wcl, g_Wcat_lo);
    cudaGetSymbolAddress((void**)&Woh, g_Wo_hi);
    cudaGetSymbolAddress((void**)&Wol, g_Wo_lo);

    const int nq = MROWS * DIMN;
    const int nw = DIMN * DIMN;

    tohalf_kernel<<<nq / 4 / 256, 256>>>(q, qhi, nq);
    tohalf_kernel<<<nw / 4 / 256, 256>>>(Wq, Wch, nw);          // hi only (x1)
    tohalf_kernel<<<nw / 4 / 256, 256>>>(Wk, Wch + nw, nw);     // hi only (x1)
    split_kernel<<<nw / 4 / 256, 256>>>(Wv, Wch + 2 * nw, Wcl + 2 * nw, nw);
    split_kernel<<<nw / 4 / 256, 256>>>(Wo, Woh, Wol, nw);

    cudaFuncSetAttribute(gemm_f16x2<false, true>,
                         cudaFuncAttributeMaxDynamicSharedMemorySize, GEMM_SMEM);
    cudaFuncSetAttribute(gemm_f16x2<true, false>,
                         cudaFuncAttributeMaxDynamicSharedMemorySize, GEMM_SMEM);
    cudaFuncSetAttribute(attn_mma_kernel,
                         cudaFuncAttributeMaxDynamicSharedMemorySize, ATTN_SMEM);

    // Fused QKV projection -> fp16 hi (+lo for V columns only).
    // Q/K columns (n0 < 2048): x1 MMAs; V columns (n0 >= 2048): x2.
    gemm_f16x2<false, true><<<dim3(PLD / 128, MROWS / 128), 256, GEMM_SMEM>>>(
        qhi, Wch, Wcl, nullptr, nullptr, QKVhi, QKVlo, PLD, 2048, 2048);

    // Tensor-core flash attention -> fp16 hi O
    attn_mma_kernel<<<dim3(SEQ / QROWS, BATCH * HEADS), ATHREADS, ATTN_SMEM>>>(
        pe, QKVhi, QKVlo, Ohi);

    // Output projection + bias -> fp32 out (x2 everywhere)
    gemm_f16x2<true, false><<<dim3(DIMN / 128, MROWS / 128), 256, GEMM_SMEM>>>(
        Ohi, Woh, Wol, bo, out, nullptr, nullptr, DIMN, 0, 0);
}

// round 8
// speedup vs baseline: 1.0857x; 1.0857x over previous
#include <cuda_runtime.h>
#include <cuda_fp16.h>
#include <cstdint>
#include <math.h>

// ---------------------------------------------------------------------------
// Problem constants
// ---------------------------------------------------------------------------
#define BATCH  32
#define SEQ    480
#define DIMN   1024
#define HEADS  16
#define HD     64
#define MROWS  (BATCH * SEQ)        // 15360
#define PLD    3072                 // fused QKV projection row stride
#define LOG2E  1.4426950408889634f
#define SCALE_LOG2E (0.125f * LOG2E)

// ---------------------------------------------------------------------------
// Device scratch (allocation-free)
// ---------------------------------------------------------------------------
__device__ __half g_QKVhi[(size_t)MROWS * PLD];
__device__ __half g_QKVlo[(size_t)MROWS * PLD];   // only V columns written/read
__device__ __half g_qhi[(size_t)MROWS * DIMN];
__device__ __half g_Ohi[(size_t)MROWS * DIMN];
__device__ __half g_Wcat_hi[(size_t)PLD * DIMN];  // [Wq;Wk;Wv]
__device__ __half g_Wcat_lo[(size_t)PLD * DIMN];  // only Wv part read
__device__ __half g_Wo_hi[(size_t)DIMN * DIMN];
__device__ __half g_Wo_lo[(size_t)DIMN * DIMN];
__device__ float  g_pe2[(size_t)SEQ * SEQ];       // pe * log2e

// ---------------------------------------------------------------------------
// PTX helpers (sm_80-era, arch-portable: mma.sync / ldmatrix / cp.async)
// ---------------------------------------------------------------------------
__device__ __forceinline__ uint32_t smem_to_u32(const void* p) {
    uint32_t a;
    asm("{ .reg .u64 t; cvta.to.shared.u64 t, %1; cvt.u32.u64 %0, t; }"
        : "=r"(a) : "l"(p));
    return a;
}

__device__ __forceinline__ void mma16816(float* d, const uint32_t* a,
                                         const uint32_t* b) {
    asm volatile(
        "mma.sync.aligned.m16n8k16.row.col.f32.f16.f16.f32 "
        "{%0,%1,%2,%3}, {%4,%5,%6,%7}, {%8,%9}, {%0,%1,%2,%3};"
        : "+f"(d[0]), "+f"(d[1]), "+f"(d[2]), "+f"(d[3])
        : "r"(a[0]), "r"(a[1]), "r"(a[2]), "r"(a[3]),
          "r"(b[0]), "r"(b[1]));
}

__device__ __forceinline__ void ldsm_x4(uint32_t* r, uint32_t saddr) {
    asm volatile(
        "ldmatrix.sync.aligned.m8n8.x4.shared.b16 {%0,%1,%2,%3}, [%4];"
        : "=r"(r[0]), "=r"(r[1]), "=r"(r[2]), "=r"(r[3]) : "r"(saddr));
}

__device__ __forceinline__ void ldsm_x4_t(uint32_t* r, uint32_t saddr) {
    asm volatile(
        "ldmatrix.sync.aligned.m8n8.x4.trans.shared.b16 {%0,%1,%2,%3}, [%4];"
        : "=r"(r[0]), "=r"(r[1]), "=r"(r[2]), "=r"(r[3]) : "r"(saddr));
}

__device__ __forceinline__ void cp16(uint32_t s, const void* g) {
    asm volatile("cp.async.cg.shared.global [%0], [%1], 16;"
                 :: "r"(s), "l"(g));
}
#define CP_COMMIT() asm volatile("cp.async.commit_group;" ::: "memory")
#define CP_WAIT2()  asm volatile("cp.async.wait_group 2;"  ::: "memory")
#define CP_WAIT1()  asm volatile("cp.async.wait_group 1;"  ::: "memory")

__device__ __forceinline__ uint32_t pack_h2(float a, float b) {
    __half2 h = __half2{__float2half_rn(a), __float2half_rn(b)};
    return *(uint32_t*)&h;
}

// 64B-row swizzle (rows of 32 halves): chunk c in 0..3
__device__ __forceinline__ uint32_t sw64(int row, int chunk) {
    return (uint32_t)(row * 64 + ((chunk ^ ((row >> 1) & 3)) << 4));
}
// 128B-row swizzle (rows of 64 halves): chunk c in 0..7
__device__ __forceinline__ uint32_t sw128(int row, int chunk) {
    return (uint32_t)(row * 128 + ((chunk ^ (row & 7)) << 4));
}

// ---------------------------------------------------------------------------
// Conversion kernels
// ---------------------------------------------------------------------------
__global__ __launch_bounds__(256)
void split_kernel(const float* __restrict__ x,
                  __half* __restrict__ hi,
                  __half* __restrict__ lo, int n)
{
    int i = (blockIdx.x * 256 + threadIdx.x) * 4;
    if (i >= n) return;
    float4 v = *(const float4*)(x + i);
    float vv[4] = {v.x, v.y, v.z, v.w};
    __half h[4], l[4];
#pragma unroll
    for (int j = 0; j < 4; j++) {
        h[j] = __float2half_rn(vv[j]);
        l[j] = __float2half_rn(vv[j] - __half2float(h[j]));
    }
    __half2* hp = (__half2*)(hi + i);
    __half2* lp = (__half2*)(lo + i);
    hp[0] = __half2{h[0], h[1]};
    hp[1] = __half2{h[2], h[3]};
    lp[0] = __half2{l[0], l[1]};
    lp[1] = __half2{l[2], l[3]};
}

__global__ __launch_bounds__(256)
void tohalf_kernel(const float* __restrict__ x,
                   __half* __restrict__ hi, int n)
{
    int i = (blockIdx.x * 256 + threadIdx.x) * 4;
    if (i >= n) return;
    float4 v = *(const float4*)(x + i);
    __half2* hp = (__half2*)(hi + i);
    hp[0] = __half2{__float2half_rn(v.x), __float2half_rn(v.y)};
    hp[1] = __half2{__float2half_rn(v.z), __float2half_rn(v.w)};
}

__global__ __launch_bounds__(256)
void scale_kernel(const float* __restrict__ x, float* __restrict__ y, int n)
{
    int i = (blockIdx.x * 256 + threadIdx.x) * 4;
    if (i >= n) return;
    float4 v = *(const float4*)(x + i);
    v.x *= LOG2E; v.y *= LOG2E; v.z *= LOG2E; v.w *= LOG2E;
    *(float4*)(y + i) = v;
}

// ---------------------------------------------------------------------------
// fp16 tensor-core GEMM: C = Ah @ Bh^T  (+ Ah @ Bl^T for CTAs with n0>=n_x2)
// 64B-row swizzled smem, 4-stage cp.async ring, ONE sync per stage.
// CTA tile 128x128, BK=32, 256 thr, 2 CTAs/SM.
// ---------------------------------------------------------------------------
#define TILE_B 8192                      // 128 rows * 64B
#define OFF_AH 0
#define OFF_BH (1 * TILE_B)
#define OFF_BL (2 * TILE_B)
#define BUF_B  (3 * TILE_B)              // 24576 per stage
#define GEMM_SMEM (4 * BUF_B)            // 98304

template <bool BIAS, bool HOUT>
__global__ __launch_bounds__(256, 2)
void gemm_f16x2(const __half* __restrict__ Ahi,
                const __half* __restrict__ Bhi,
                const __half* __restrict__ Blo,
                const float* __restrict__ bias,
                float* __restrict__ C,
                __half* __restrict__ Chi,
                __half* __restrict__ Clo, int ldc, int lo_min, int n_x2)
{
    extern __shared__ __align__(128) char smem[];
    const uint32_t sb = smem_to_u32(smem);

    const int tid  = threadIdx.x;
    const int lane = tid & 31;
    const int wid  = tid >> 5;
    const int wm   = wid >> 1;
    const int wn   = wid & 1;
    const int m0   = blockIdx.y * 128;
    const int n0   = blockIdx.x * 128;
    const bool do2 = (n0 >= n_x2);

    // writer mapping
    const int lrow0 = tid >> 2;          // 0..63
    const int lch   = (tid & 3) * 8;     // halves offset
    const uint32_t s0 = sw64(lrow0, tid & 3);
    const uint32_t s1 = s0 + 64 * 64;    // row+64: same xor (row>>1)&3 invariant mod 4

    const __half* gAh = Ahi + (size_t)(m0 + lrow0) * DIMN + lch;
    const __half* gBh = Bhi + (size_t)(n0 + lrow0) * DIMN + lch;
    const __half* gBl = Blo + (size_t)(n0 + lrow0) * DIMN + lch;
    const size_t rstep = (size_t)64 * DIMN;

    // reader mapping (xor invariant under row+16 / row+32)
    const int Ra   = wm * 32 + (lane & 15);
    const int xorA = (Ra >> 1) & 3;
    const int ca   = lane >> 4;                     // + 2*kk
    const uint32_t aBase = (uint32_t)(Ra * 64);
    const int Rb   = wn * 64 + ((lane >> 4) << 3) + (lane & 7);
    const int xorB = (Rb >> 1) & 3;
    const int cb   = (lane >> 3) & 1;               // + 2*kk
    const uint32_t bBase = (uint32_t)(Rb * 64);

    float acc[2][8][4];
#pragma unroll
    for (int i = 0; i < 2; i++)
#pragma unroll
        for (int j = 0; j < 8; j++)
#pragma unroll
            for (int c = 0; c < 4; c++) acc[i][j][c] = 0.f;

    auto issue_loads = [&](int s) {
        const int k0 = s * 32;
        const uint32_t base = sb + (s & 3) * BUF_B;
        cp16(base + OFF_AH + s0, gAh + k0);
        cp16(base + OFF_AH + s1, gAh + k0 + rstep);
        cp16(base + OFF_BH + s0, gBh + k0);
        cp16(base + OFF_BH + s1, gBh + k0 + rstep);
        if (do2) {
            cp16(base + OFF_BL + s0, gBl + k0);
            cp16(base + OFF_BL + s1, gBl + k0 + rstep);
        }
    };

#pragma unroll
    for (int st = 0; st < 3; st++) { issue_loads(st); CP_COMMIT(); }

    for (int s = 0; s < 32; s++) {
        CP_WAIT2();
        __syncthreads();                 // stage s ready; buf (s+3)%4 free

        if (s + 3 < 32) issue_loads(s + 3);
        CP_COMMIT();

        const uint32_t base = sb + (s & 3) * BUF_B;
#pragma unroll
        for (int kk = 0; kk < 2; kk++) {
            uint32_t ah[2][4];
#pragma unroll
            for (int mi = 0; mi < 2; mi++)
                ldsm_x4(ah[mi], base + OFF_AH + aBase + mi * 1024 +
                                (uint32_t)(((ca + 2 * kk) ^ xorA) << 4));
            uint32_t bh[4][4], bl[4][4];
#pragma unroll
            for (int bn = 0; bn < 4; bn++)
                ldsm_x4(bh[bn], base + OFF_BH + bBase + bn * 1024 +
                                (uint32_t)(((cb + 2 * kk) ^ xorB) << 4));
            if (do2) {
#pragma unroll
                for (int bn = 0; bn < 4; bn++)
                    ldsm_x4(bl[bn], base + OFF_BL + bBase + bn * 1024 +
                                    (uint32_t)(((cb + 2 * kk) ^ xorB) << 4));
            }
#pragma unroll
            for (int mi = 0; mi < 2; mi++)
#pragma unroll
                for (int ni = 0; ni < 8; ni++) {
                    mma16816(acc[mi][ni], ah[mi], &bh[ni >> 1][(ni & 1) * 2]);
                    if (do2)
                        mma16816(acc[mi][ni], ah[mi], &bl[ni >> 1][(ni & 1) * 2]);
                }
        }
    }

    const bool wlo = HOUT && (n0 >= lo_min);
#pragma unroll
    for (int mi = 0; mi < 2; mi++) {
        const int row = m0 + wm * 32 + mi * 16 + (lane >> 2);
#pragma unroll
        for (int ni = 0; ni < 8; ni++) {
            const int col = n0 + wn * 64 + ni * 8 + ((lane & 3) << 1);
            if (HOUT) {
                float v00 = acc[mi][ni][0], v01 = acc[mi][ni][1];
                float v10 = acc[mi][ni][2], v11 = acc[mi][ni][3];
                __half h00 = __float2half_rn(v00), h01 = __float2half_rn(v01);
                __half h10 = __float2half_rn(v10), h11 = __float2half_rn(v11);
                *(__half2*)(Chi + (size_t)row * ldc + col)       = __half2{h00, h01};
                *(__half2*)(Chi + (size_t)(row + 8) * ldc + col) = __half2{h10, h11};
                if (wlo) {
                    __half l00 = __float2half_rn(v00 - __half2float(h00));
                    __half l01 = __float2half_rn(v01 - __half2float(h01));
                    __half l10 = __float2half_rn(v10 - __half2float(h10));
                    __half l11 = __float2half_rn(v11 - __half2float(h11));
                    *(__half2*)(Clo + (size_t)row * ldc + col)       = __half2{l00, l01};
                    *(__half2*)(Clo + (size_t)(row + 8) * ldc + col) = __half2{l10, l11};
                }
            } else {
                float b0 = 0.f, b1 = 0.f;
                if (BIAS) { b0 = bias[col]; b1 = bias[col + 1]; }
                float2 v0 = make_float2(acc[mi][ni][0] + b0, acc[mi][ni][1] + b1);
                float2 v1 = make_float2(acc[mi][ni][2] + b0, acc[mi][ni][3] + b1);
                *(float2*)(C + (size_t)row * ldc + col)       = v0;
                *(float2*)(C + (size_t)(row + 8) * ldc + col) = v1;
            }
        }
    }
}

// ---------------------------------------------------------------------------
// Tensor-core flash attention.
// 192 threads (6 warps x 16 q-rows = 96 rows), grid (5, B*H).
// 3-stage KV ring (Khi,Vhi,Vlo), ONE sync per block, 128B-row swizzle.
// S = Qh*Kh (x1); O = Ph*(Vh+Vl) (x2). softmax in log2 domain (exp2f).
// ---------------------------------------------------------------------------
#define QROWS 96
#define ATHREADS 192
#define KV_PLANE (64 * 128)              // 8192
#define KV_STAGE (3 * KV_PLANE)          // 24576
#define Q_OFF (3 * KV_STAGE)             // 73728
#define ATTN_SMEM (Q_OFF + QROWS * 128)  // 86016

__global__ __launch_bounds__(ATHREADS, 2)
void attn_mma_kernel(const float* __restrict__ pe2,
                     const __half* __restrict__ QKVhi,
                     const __half* __restrict__ QKVlo,
                     __half* __restrict__ Ohi)
{
    extern __shared__ __align__(128) char smem[];
    const uint32_t sb = smem_to_u32(smem);
    const int tid  = threadIdx.x;
    const int lane = tid & 31;
    const int wid  = tid >> 5;
    const int q0   = blockIdx.x * QROWS;
    const int bh   = blockIdx.y;
    const int b    = bh >> 4;
    const int h    = bh & 15;

    const size_t rowbase = (size_t)b * SEQ;

    // KV stage loader (issue only; no commit)
    auto load_kv = [&](int kb) {
        const int k0 = kb * 64;
        const uint32_t stg = sb + (uint32_t)((kb % 3) * KV_STAGE);
        for (int c = tid; c < 1536; c += ATHREADS) {
            const int plane = c >> 9;           // 0 Khi 1 Vhi 2 Vlo
            const int idx = c & 511;
            const int row = idx >> 3, ch = idx & 7;
            int kr = k0 + row;
            if (kr >= SEQ) kr = SEQ - 1;        // clamp; masked via S later
            const __half* base = (plane == 2) ? QKVlo : QKVhi;
            const int coloff = (plane == 0) ? DIMN : 2 * DIMN;
            cp16(stg + plane * KV_PLANE + sw128(row, ch),
                 base + (rowbase + kr) * PLD + coloff + h * HD + ch * 8);
        }
    };

    // group 0: Q + kv0;  group 1: kv1
    {
        const size_t gq = (rowbase + q0) * PLD + h * HD;
        for (int c = tid; c < QROWS * 8; c += ATHREADS) {
            const int row = c >> 3, ch = c & 7;
            cp16(sb + Q_OFF + sw128(row, ch), QKVhi + gq + (size_t)row * PLD + ch * 8);
        }
    }
    load_kv(0); CP_COMMIT();
    load_kv(1); CP_COMMIT();

    // reader mappings
    const int Rq   = wid * 16 + (lane & 15);
    const int xorQ = Rq & 7;
    const int cqa  = lane >> 4;                 // + 2*ks
    const uint32_t qBase = sb + Q_OFF + (uint32_t)(Rq * 128);
    const int Rk   = ((lane >> 4) << 3) + (lane & 7);    // + ng*16
    const int xorK = lane & 7;                  // (Rk&7), invariant mod 16
    const int ckb  = (lane >> 3) & 1;           // + 2*ks
    const int Rv   = lane & 15;                 // + ks*16
    const int xorV = lane & 7;
    const int cvb  = lane >> 4;                 // + 2*dg

    const int r0  = lane >> 2;
    const int c2  = (lane & 3) * 2;
    const int qr  = q0 + wid * 16 + r0;
    const float* peA = pe2 + (size_t)qr * SEQ;
    const float* peB = pe2 + (size_t)(qr + 8) * SEQ;

    float o[8][4];
#pragma unroll
    for (int i = 0; i < 8; i++)
#pragma unroll
        for (int c = 0; c < 4; c++) o[i][c] = 0.f;
    float mrow0 = -INFINITY, mrow1 = -INFINITY;
    float lsum0 = 0.f, lsum1 = 0.f;

    for (int kb = 0; kb < 8; kb++) {
        CP_WAIT1();
        __syncthreads();                 // stage kb ready; buf (kb+2)%3 free

        if (kb + 2 < 8) load_kv(kb + 2);
        CP_COMMIT();

        const uint32_t kvbase = sb + (uint32_t)((kb % 3) * KV_STAGE);
        const int k0 = kb * 64;

        // ---- S = Qh @ Kh^T ----
        float s[8][4];
#pragma unroll
        for (int i = 0; i < 8; i++)
#pragma unroll
            for (int c = 0; c < 4; c++) s[i][c] = 0.f;

#pragma unroll
        for (int ks = 0; ks < 4; ks++) {
            uint32_t qh[4];
            ldsm_x4(qh, qBase + (uint32_t)((((cqa + 2 * ks) ^ xorQ)) << 4));
            uint32_t kh[4][4];
#pragma unroll
            for (int ng = 0; ng < 4; ng++)
                ldsm_x4(kh[ng], kvbase + (uint32_t)((Rk + ng * 16) * 128) +
                                (uint32_t)((((ckb + 2 * ks) ^ xorK)) << 4));
#pragma unroll
            for (int ni = 0; ni < 8; ni++)
                mma16816(s[ni], qh, &kh[ni >> 1][(ni & 1) * 2]);
        }

        // ---- scale (log2 domain) + pe bias + mask ----
#pragma unroll
        for (int ni = 0; ni < 8; ni++) {
            const int kc = k0 + ni * 8 + c2;
            if (kc < SEQ) {
                float2 pA = *(const float2*)(peA + kc);
                float2 pB = *(const float2*)(peB + kc);
                s[ni][0] = s[ni][0] * SCALE_LOG2E + pA.x;
                s[ni][1] = s[ni][1] * SCALE_LOG2E + pA.y;
                s[ni][2] = s[ni][2] * SCALE_LOG2E + pB.x;
                s[ni][3] = s[ni][3] * SCALE_LOG2E + pB.y;
            } else {
                s[ni][0] = -1e30f; s[ni][1] = -1e30f;
                s[ni][2] = -1e30f; s[ni][3] = -1e30f;
            }
        }

        // ---- online softmax (base-2) ----
        float m0 = -INFINITY, m1 = -INFINITY;
#pragma unroll
        for (int ni = 0; ni < 8; ni++) {
            m0 = fmaxf(m0, fmaxf(s[ni][0], s[ni][1]));
            m1 = fmaxf(m1, fmaxf(s[ni][2], s[ni][3]));
        }
        m0 = fmaxf(m0, __shfl_xor_sync(0xffffffffu, m0, 1));
        m0 = fmaxf(m0, __shfl_xor_sync(0xffffffffu, m0, 2));
        m1 = fmaxf(m1, __shfl_xor_sync(0xffffffffu, m1, 1));
        m1 = fmaxf(m1, __shfl_xor_sync(0xffffffffu, m1, 2));

        const float mn0 = fmaxf(mrow0, m0);
        const float mn1 = fmaxf(mrow1, m1);
        const float f0 = exp2f(mrow0 - mn0);
        const float f1 = exp2f(mrow1 - mn1);
        mrow0 = mn0; mrow1 = mn1;

        float sum0 = 0.f, sum1 = 0.f;
        uint32_t phi[4][4];
#pragma unroll
        for (int ks = 0; ks < 4; ks++) {
            const int n0i = 2 * ks, n1i = 2 * ks + 1;
            float p00 = exp2f(s[n0i][0] - mn0), p01 = exp2f(s[n0i][1] - mn0);
            float p02 = exp2f(s[n0i][2] - mn1), p03 = exp2f(s[n0i][3] - mn1);
            float p10 = exp2f(s[n1i][0] - mn0), p11 = exp2f(s[n1i][1] - mn0);
            float p12 = exp2f(s[n1i][2] - mn1), p13 = exp2f(s[n1i][3] - mn1);
            sum0 += p00 + p01 + p10 + p11;
            sum1 += p02 + p03 + p12 + p13;
            phi[ks][0] = pack_h2(p00, p01);
            phi[ks][1] = pack_h2(p02, p03);
            phi[ks][2] = pack_h2(p10, p11);
            phi[ks][3] = pack_h2(p12, p13);
        }
        lsum0 = lsum0 * f0 + sum0;
        lsum1 = lsum1 * f1 + sum1;

#pragma unroll
        for (int ni = 0; ni < 8; ni++) {
            o[ni][0] *= f0; o[ni][1] *= f0;
            o[ni][2] *= f1; o[ni][3] *= f1;
        }

        // ---- O += Ph @ (Vh + Vl) ----
#pragma unroll
        for (int ks = 0; ks < 4; ks++) {
            uint32_t vh[4][4], vl[4][4];
#pragma unroll
            for (int dg = 0; dg < 4; dg++) {
                const uint32_t va = kvbase + (uint32_t)((Rv + ks * 16) * 128) +
                                    (uint32_t)((((cvb + 2 * dg) ^ xorV)) << 4);
                ldsm_x4_t(vh[dg], va + 1 * KV_PLANE);
                ldsm_x4_t(vl[dg], va + 2 * KV_PLANE);
            }
#pragma unroll
            for (int ni = 0; ni < 8; ni++) {
                mma16816(o[ni], phi[ks], &vh[ni >> 1][(ni & 1) * 2]);
                mma16816(o[ni], phi[ks], &vl[ni >> 1][(ni & 1) * 2]);
            }
        }
    }

    // ---- finalize ----
    lsum0 += __shfl_xor_sync(0xffffffffu, lsum0, 1);
    lsum0 += __shfl_xor_sync(0xffffffffu, lsum0, 2);
    lsum1 += __shfl_xor_sync(0xffffffffu, lsum1, 1);
    lsum1 += __shfl_xor_sync(0xffffffffu, lsum1, 2);
    const float inv0 = 1.f / lsum0;
    const float inv1 = 1.f / lsum1;

    const size_t orow0 = (rowbase + qr) * DIMN + h * HD;
    const size_t orow1 = (rowbase + qr + 8) * DIMN + h * HD;
#pragma unroll
    for (int ni = 0; ni < 8; ni++) {
        const int d = ni * 8 + c2;
        *(__half2*)(Ohi + orow0 + d) =
            __half2{__float2half_rn(o[ni][0] * inv0), __float2half_rn(o[ni][1] * inv0)};
        *(__half2*)(Ohi + orow1 + d) =
            __half2{__float2half_rn(o[ni][2] * inv1), __float2half_rn(o[ni][3] * inv1)};
    }
}

// ---------------------------------------------------------------------------
extern "C" void kernel_launch(void* const* d_in, const int* in_sizes, int n_in,
                              void* d_out, int out_size)
{
    const float* q  = (const float*)d_in[0];
    const float* Wq = (const float*)d_in[1];
    const float* Wk = (const float*)d_in[2];
    const float* Wv = (const float*)d_in[3];
    const float* pe = (const float*)d_in[4];
    const float* Wo = (const float*)d_in[5];
    const float* bo = (const float*)d_in[6];
    float* out = (float*)d_out;

    __half *QKVhi, *QKVlo, *qhi, *Ohi, *Wch, *Wcl, *Woh, *Wol;
    float* pe2;
    cudaGetSymbolAddress((void**)&QKVhi, g_QKVhi);
    cudaGetSymbolAddress((void**)&QKVlo, g_QKVlo);
    cudaGetSymbolAddress((void**)&qhi, g_qhi);
    cudaGetSymbolAddress((void**)&Ohi, g_Ohi);
    cudaGetSymbolAddress((void**)&Wch, g_Wcat_hi);
    cudaGetSymbolAddress((void**)&Wcl, g_Wcat_lo);
    cudaGetSymbolAddress((void**)&Woh, g_Wo_hi);
    cudaGetSymbolAddress((void**)&Wol, g_Wo_lo);
    cudaGetSymbolAddress((void**)&pe2, g_pe2);

    const int nq = MROWS * DIMN;
    const int nw = DIMN * DIMN;
    const int np = SEQ * SEQ;                 // 230400

    tohalf_kernel<<<nq / 4 / 256, 256>>>(q, qhi, nq);
    tohalf_kernel<<<nw / 4 / 256, 256>>>(Wq, Wch, nw);
    tohalf_kernel<<<nw / 4 / 256, 256>>>(Wk, Wch + nw, nw);
    split_kernel<<<nw / 4 / 256, 256>>>(Wv, Wch + 2 * nw, Wcl + 2 * nw, nw);
    split_kernel<<<nw / 4 / 256, 256>>>(Wo, Woh, Wol, nw);
    scale_kernel<<<np / 4 / 256, 256>>>(pe, pe2, np);

    cudaFuncSetAttribute(gemm_f16x2<false, true>,
                         cudaFuncAttributeMaxDynamicSharedMemorySize, GEMM_SMEM);
    cudaFuncSetAttribute(gemm_f16x2<true, false>,
                         cudaFuncAttributeMaxDynamicSharedMemorySize, GEMM_SMEM);
    cudaFuncSetAttribute(attn_mma_kernel,
                         cudaFuncAttributeMaxDynamicSharedMemorySize, ATTN_SMEM);

    // Fused QKV projection -> fp16 hi (+lo for V columns only).
    gemm_f16x2<false, true><<<dim3(PLD / 128, MROWS / 128), 256, GEMM_SMEM>>>(
        qhi, Wch, Wcl, nullptr, nullptr, QKVhi, QKVlo, PLD, 2048, 2048);

    // Tensor-core flash attention -> fp16 hi O
    attn_mma_kernel<<<dim3(SEQ / QROWS, BATCH * HEADS), ATHREADS, ATTN_SMEM>>>(
        pe2, QKVhi, QKVlo, Ohi);

    // Output projection + bias -> fp32 out (x2)
    gemm_f16x2<true, false><<<dim3(DIMN / 128, MROWS / 128), 256, GEMM_SMEM>>>(
        Ohi, Woh, Wol, bo, out, nullptr, nullptr, DIMN, 0, 0);
}

// round 9
// speedup vs baseline: 1.7864x; 1.6453x over previous
#include <cuda_runtime.h>
#include <cuda_fp16.h>
#include <cstdint>
#include <math.h>

// ---------------------------------------------------------------------------
// Problem constants
// ---------------------------------------------------------------------------
#define BATCH  32
#define SEQ    480
#define DIMN   1024
#define HEADS  16
#define HD     64
#define MROWS  (BATCH * SEQ)        // 15360
#define PLD    3072                 // fused QKV projection row stride
#define LOG2E  1.4426950408889634f
#define SCALE_LOG2E (0.125f * LOG2E)

// ---------------------------------------------------------------------------
// Device scratch (allocation-free)
// ---------------------------------------------------------------------------
__device__ __half g_QKVhi[(size_t)MROWS * PLD];
__device__ __half g_qhi[(size_t)MROWS * DIMN];
__device__ __half g_Ohi[(size_t)MROWS * DIMN];
__device__ __half g_Wcat_hi[(size_t)PLD * DIMN];  // [Wq;Wk;Wv]
__device__ __half g_Wo_hi[(size_t)DIMN * DIMN];
__device__ float  g_pe2[(size_t)SEQ * SEQ];       // pe * log2e

// ---------------------------------------------------------------------------
// PTX helpers (sm_80-era, arch-portable: mma.sync / ldmatrix / cp.async)
// ---------------------------------------------------------------------------
__device__ __forceinline__ uint32_t smem_to_u32(const void* p) {
    uint32_t a;
    asm("{ .reg .u64 t; cvta.to.shared.u64 t, %1; cvt.u32.u64 %0, t; }"
        : "=r"(a) : "l"(p));
    return a;
}

__device__ __forceinline__ void mma16816(float* d, const uint32_t* a,
                                         const uint32_t* b) {
    asm volatile(
        "mma.sync.aligned.m16n8k16.row.col.f32.f16.f16.f32 "
        "{%0,%1,%2,%3}, {%4,%5,%6,%7}, {%8,%9}, {%0,%1,%2,%3};"
        : "+f"(d[0]), "+f"(d[1]), "+f"(d[2]), "+f"(d[3])
        : "r"(a[0]), "r"(a[1]), "r"(a[2]), "r"(a[3]),
          "r"(b[0]), "r"(b[1]));
}

__device__ __forceinline__ void ldsm_x4(uint32_t* r, uint32_t saddr) {
    asm volatile(
        "ldmatrix.sync.aligned.m8n8.x4.shared.b16 {%0,%1,%2,%3}, [%4];"
        : "=r"(r[0]), "=r"(r[1]), "=r"(r[2]), "=r"(r[3]) : "r"(saddr));
}

__device__ __forceinline__ void ldsm_x4_t(uint32_t* r, uint32_t saddr) {
    asm volatile(
        "ldmatrix.sync.aligned.m8n8.x4.trans.shared.b16 {%0,%1,%2,%3}, [%4];"
        : "=r"(r[0]), "=r"(r[1]), "=r"(r[2]), "=r"(r[3]) : "r"(saddr));
}

__device__ __forceinline__ void cp16(uint32_t s, const void* g) {
    asm volatile("cp.async.cg.shared.global [%0], [%1], 16;"
                 :: "r"(s), "l"(g));
}
#define CP_COMMIT() asm volatile("cp.async.commit_group;" ::: "memory")
#define CP_WAIT1()  asm volatile("cp.async.wait_group 1;"  ::: "memory")

__device__ __forceinline__ uint32_t pack_h2(float a, float b) {
    __half2 h = __half2{__float2half_rn(a), __float2half_rn(b)};
    return *(uint32_t*)&h;
}

// 128B-row swizzle (rows of 64 halves): chunk c in 0..7
__device__ __forceinline__ uint32_t sw128(int row, int chunk) {
    return (uint32_t)(row * 128 + ((chunk ^ (row & 7)) << 4));
}

// ---------------------------------------------------------------------------
// Conversion kernels
// ---------------------------------------------------------------------------
__global__ __launch_bounds__(256)
void tohalf_kernel(const float* __restrict__ x,
                   __half* __restrict__ hi, int n)
{
    int i = (blockIdx.x * 256 + threadIdx.x) * 4;
    if (i >= n) return;
    float4 v = *(const float4*)(x + i);
    __half2* hp = (__half2*)(hi + i);
    hp[0] = __half2{__float2half_rn(v.x), __float2half_rn(v.y)};
    hp[1] = __half2{__float2half_rn(v.z), __float2half_rn(v.w)};
}

__global__ __launch_bounds__(256)
void scale_kernel(const float* __restrict__ x, float* __restrict__ y, int n)
{
    int i = (blockIdx.x * 256 + threadIdx.x) * 4;
    if (i >= n) return;
    float4 v = *(const float4*)(x + i);
    v.x *= LOG2E; v.y *= LOG2E; v.z *= LOG2E; v.w *= LOG2E;
    *(float4*)(y + i) = v;
}

// ---------------------------------------------------------------------------
// fp16 x1 tensor-core GEMM: C = Ah @ Bh^T (+bias).
// CTA tile 128x128, BK=64, 3-stage cp.async ring, ONE sync per stage,
// 128B-row sw128 swizzle, 256 thr, 2 CTAs/SM.
// ---------------------------------------------------------------------------
#define TILE_B (128 * 128)               // 16384 = 128 rows x 128B
#define OFF_A  0
#define OFF_B  TILE_B
#define BUF_B  (2 * TILE_B)              // 32768 per stage
#define GEMM_SMEM (3 * BUF_B)            // 98304

template <bool BIAS, bool HOUT>
__global__ __launch_bounds__(256, 2)
void gemm_f16x1(const __half* __restrict__ Ahi,
                const __half* __restrict__ Bhi,
                const float* __restrict__ bias,
                float* __restrict__ C,
                __half* __restrict__ Chi, int ldc)
{
    extern __shared__ __align__(128) char smem[];
    const uint32_t sb = smem_to_u32(smem);

    const int tid  = threadIdx.x;
    const int lane = tid & 31;
    const int wid  = tid >> 5;
    const int wm   = wid >> 1;
    const int wn   = wid & 1;
    const int m0   = blockIdx.y * 128;
    const int n0   = blockIdx.x * 128;

    // writer mapping: 1024 chunks/plane, 4 rounds of 256
    const int wrow = tid >> 3;           // 0..31 (+32 per round)
    const int wch  = tid & 7;
    const __half* gA = Ahi + (size_t)(m0 + wrow) * DIMN + wch * 8;
    const __half* gB = Bhi + (size_t)(n0 + wrow) * DIMN + wch * 8;
    uint32_t wsw[4];
#pragma unroll
    for (int i = 0; i < 4; i++) wsw[i] = sw128(wrow + 32 * i, wch);

    // reader mapping (xor = row & 7, invariant under +16/+32 row steps)
    const int Ra   = wm * 32 + (lane & 15);
    const int xorA = Ra & 7;
    const int ca   = lane >> 4;                     // + 2*kk
    const uint32_t aBase = (uint32_t)(Ra * 128);
    const int Rb   = wn * 64 + ((lane >> 4) << 3) + (lane & 7);
    const int xorB = Rb & 7;
    const int cb   = (lane >> 3) & 1;               // + 2*kk
    const uint32_t bBase = (uint32_t)(Rb * 128);

    float acc[2][8][4];
#pragma unroll
    for (int i = 0; i < 2; i++)
#pragma unroll
        for (int j = 0; j < 8; j++)
#pragma unroll
            for (int c = 0; c < 4; c++) acc[i][j][c] = 0.f;

    auto issue_loads = [&](int s) {
        const int k0 = s * 64;
        const uint32_t base = sb + (uint32_t)((s % 3) * BUF_B);
#pragma unroll
        for (int i = 0; i < 4; i++) {
            cp16(base + OFF_A + wsw[i], gA + (size_t)(32 * i) * DIMN + k0);
            cp16(base + OFF_B + wsw[i], gB + (size_t)(32 * i) * DIMN + k0);
        }
    };

    issue_loads(0); CP_COMMIT();
    issue_loads(1); CP_COMMIT();

    for (int s = 0; s < 16; s++) {
        CP_WAIT1();
        __syncthreads();                 // stage s ready; buf (s+2)%3 free

        if (s + 2 < 16) issue_loads(s + 2);
        CP_COMMIT();

        const uint32_t base = sb + (uint32_t)((s % 3) * BUF_B);
#pragma unroll
        for (int kk = 0; kk < 4; kk++) {
            uint32_t ah[2][4];
#pragma unroll
            for (int mi = 0; mi < 2; mi++)
                ldsm_x4(ah[mi], base + OFF_A + aBase + mi * 2048 +
                                (uint32_t)(((ca + 2 * kk) ^ xorA) << 4));
            uint32_t bh[4][4];
#pragma unroll
            for (int bn = 0; bn < 4; bn++)
                ldsm_x4(bh[bn], base + OFF_B + bBase + bn * 2048 +
                                (uint32_t)(((cb + 2 * kk) ^ xorB) << 4));
#pragma unroll
            for (int mi = 0; mi < 2; mi++)
#pragma unroll
                for (int ni = 0; ni < 8; ni++)
                    mma16816(acc[mi][ni], ah[mi], &bh[ni >> 1][(ni & 1) * 2]);
        }
    }

#pragma unroll
    for (int mi = 0; mi < 2; mi++) {
        const int row = m0 + wm * 32 + mi * 16 + (lane >> 2);
#pragma unroll
        for (int ni = 0; ni < 8; ni++) {
            const int col = n0 + wn * 64 + ni * 8 + ((lane & 3) << 1);
            if (HOUT) {
                *(__half2*)(Chi + (size_t)row * ldc + col) =
                    __half2{__float2half_rn(acc[mi][ni][0]),
                            __float2half_rn(acc[mi][ni][1])};
                *(__half2*)(Chi + (size_t)(row + 8) * ldc + col) =
                    __half2{__float2half_rn(acc[mi][ni][2]),
                            __float2half_rn(acc[mi][ni][3])};
            } else {
                float b0 = 0.f, b1 = 0.f;
                if (BIAS) { b0 = bias[col]; b1 = bias[col + 1]; }
                float2 v0 = make_float2(acc[mi][ni][0] + b0, acc[mi][ni][1] + b1);
                float2 v1 = make_float2(acc[mi][ni][2] + b0, acc[mi][ni][3] + b1);
                *(float2*)(C + (size_t)row * ldc + col)       = v0;
                *(float2*)(C + (size_t)(row + 8) * ldc + col) = v1;
            }
        }
    }
}

// ---------------------------------------------------------------------------
// Tensor-core flash attention (all x1).
// 192 threads (6 warps x 16 q-rows = 96 rows), grid (5, B*H).
// 3-stage KV ring (Khi,Vhi), ONE sync per block, 128B-row swizzle.
// softmax in log2 domain (exp2f).
// ---------------------------------------------------------------------------
#define QROWS 96
#define ATHREADS 192
#define KV_PLANE (64 * 128)              // 8192
#define KV_STAGE (2 * KV_PLANE)          // 16384
#define Q_OFF (3 * KV_STAGE)             // 49152
#define ATTN_SMEM (Q_OFF + QROWS * 128)  // 61440

__global__ __launch_bounds__(ATHREADS, 2)
void attn_mma_kernel(const float* __restrict__ pe2,
                     const __half* __restrict__ QKVhi,
                     __half* __restrict__ Ohi)
{
    extern __shared__ __align__(128) char smem[];
    const uint32_t sb = smem_to_u32(smem);
    const int tid  = threadIdx.x;
    const int lane = tid & 31;
    const int wid  = tid >> 5;
    const int q0   = blockIdx.x * QROWS;
    const int bh   = blockIdx.y;
    const int b    = bh >> 4;
    const int h    = bh & 15;

    const size_t rowbase = (size_t)b * SEQ;

    // KV stage loader: 2 planes (Khi, Vhi), 1024 chunks
    auto load_kv = [&](int kb) {
        const int k0 = kb * 64;
        const uint32_t stg = sb + (uint32_t)((kb % 3) * KV_STAGE);
        for (int c = tid; c < 1024; c += ATHREADS) {
            const int plane = c >> 9;           // 0 Khi 1 Vhi
            const int idx = c & 511;
            const int row = idx >> 3, ch = idx & 7;
            int kr = k0 + row;
            if (kr >= SEQ) kr = SEQ - 1;        // clamp; masked via S later
            const int coloff = (plane == 0) ? DIMN : 2 * DIMN;
            cp16(stg + plane * KV_PLANE + sw128(row, ch),
                 QKVhi + (rowbase + kr) * PLD + coloff + h * HD + ch * 8);
        }
    };

    // group 0: Q + kv0;  group 1: kv1
    {
        const size_t gq = (rowbase + q0) * PLD + h * HD;
        for (int c = tid; c < QROWS * 8; c += ATHREADS) {
            const int row = c >> 3, ch = c & 7;
            cp16(sb + Q_OFF + sw128(row, ch), QKVhi + gq + (size_t)row * PLD + ch * 8);
        }
    }
    load_kv(0); CP_COMMIT();
    load_kv(1); CP_COMMIT();

    // reader mappings
    const int Rq   = wid * 16 + (lane & 15);
    const int xorQ = Rq & 7;
    const int cqa  = lane >> 4;                 // + 2*ks
    const uint32_t qBase = sb + Q_OFF + (uint32_t)(Rq * 128);
    const int Rk   = ((lane >> 4) << 3) + (lane & 7);    // + ng*16
    const int xorK = lane & 7;
    const int ckb  = (lane >> 3) & 1;           // + 2*ks
    const int Rv   = lane & 15;                 // + ks*16
    const int xorV = lane & 7;
    const int cvb  = lane >> 4;                 // + 2*dg

    const int r0  = lane >> 2;
    const int c2  = (lane & 3) * 2;
    const int qr  = q0 + wid * 16 + r0;
    const float* peA = pe2 + (size_t)qr * SEQ;
    const float* peB = pe2 + (size_t)(qr + 8) * SEQ;

    float o[8][4];
#pragma unroll
    for (int i = 0; i < 8; i++)
#pragma unroll
        for (int c = 0; c < 4; c++) o[i][c] = 0.f;
    float mrow0 = -INFINITY, mrow1 = -INFINITY;
    float lsum0 = 0.f, lsum1 = 0.f;

    for (int kb = 0; kb < 8; kb++) {
        CP_WAIT1();
        __syncthreads();                 // stage kb ready; buf (kb+2)%3 free

        if (kb + 2 < 8) load_kv(kb + 2);
        CP_COMMIT();

        const uint32_t kvbase = sb + (uint32_t)((kb % 3) * KV_STAGE);
        const int k0 = kb * 64;

        // ---- S = Qh @ Kh^T ----
        float s[8][4];
#pragma unroll
        for (int i = 0; i < 8; i++)
#pragma unroll
            for (int c = 0; c < 4; c++) s[i][c] = 0.f;

#pragma unroll
        for (int ks = 0; ks < 4; ks++) {
            uint32_t qh[4];
            ldsm_x4(qh, qBase + (uint32_t)((((cqa + 2 * ks) ^ xorQ)) << 4));
            uint32_t kh[4][4];
#pragma unroll
            for (int ng = 0; ng < 4; ng++)
                ldsm_x4(kh[ng], kvbase + (uint32_t)((Rk + ng * 16) * 128) +
                                (uint32_t)((((ckb + 2 * ks) ^ xorK)) << 4));
#pragma unroll
            for (int ni = 0; ni < 8; ni++)
                mma16816(s[ni], qh, &kh[ni >> 1][(ni & 1) * 2]);
        }

        // ---- scale (log2 domain) + pe bias + mask ----
#pragma unroll
        for (int ni = 0; ni < 8; ni++) {
            const int kc = k0 + ni * 8 + c2;
            if (kc < SEQ) {
                float2 pA = *(const float2*)(peA + kc);
                float2 pB = *(const float2*)(peB + kc);
                s[ni][0] = s[ni][0] * SCALE_LOG2E + pA.x;
                s[ni][1] = s[ni][1] * SCALE_LOG2E + pA.y;
                s[ni][2] = s[ni][2] * SCALE_LOG2E + pB.x;
                s[ni][3] = s[ni][3] * SCALE_LOG2E + pB.y;
            } else {
                s[ni][0] = -1e30f; s[ni][1] = -1e30f;
                s[ni][2] = -1e30f; s[ni][3] = -1e30f;
            }
        }

        // ---- online softmax (base-2) ----
        float m0 = -INFINITY, m1 = -INFINITY;
#pragma unroll
        for (int ni = 0; ni < 8; ni++) {
            m0 = fmaxf(m0, fmaxf(s[ni][0], s[ni][1]));
            m1 = fmaxf(m1, fmaxf(s[ni][2], s[ni][3]));
        }
        m0 = fmaxf(m0, __shfl_xor_sync(0xffffffffu, m0, 1));
        m0 = fmaxf(m0, __shfl_xor_sync(0xffffffffu, m0, 2));
        m1 = fmaxf(m1, __shfl_xor_sync(0xffffffffu, m1, 1));
        m1 = fmaxf(m1, __shfl_xor_sync(0xffffffffu, m1, 2));

        const float mn0 = fmaxf(mrow0, m0);
        const float mn1 = fmaxf(mrow1, m1);
        const float f0 = exp2f(mrow0 - mn0);
        const float f1 = exp2f(mrow1 - mn1);
        mrow0 = mn0; mrow1 = mn1;

        float sum0 = 0.f, sum1 = 0.f;
        uint32_t phi[4][4];
#pragma unroll
        for (int ks = 0; ks < 4; ks++) {
            const int n0i = 2 * ks, n1i = 2 * ks + 1;
            float p00 = exp2f(s[n0i][0] - mn0), p01 = exp2f(s[n0i][1] - mn0);
            float p02 = exp2f(s[n0i][2] - mn1), p03 = exp2f(s[n0i][3] - mn1);
            float p10 = exp2f(s[n1i][0] - mn0), p11 = exp2f(s[n1i][1] - mn0);
            float p12 = exp2f(s[n1i][2] - mn1), p13 = exp2f(s[n1i][3] - mn1);
            sum0 += p00 + p01 + p10 + p11;
            sum1 += p02 + p03 + p12 + p13;
            phi[ks][0] = pack_h2(p00, p01);
            phi[ks][1] = pack_h2(p02, p03);
            phi[ks][2] = pack_h2(p10, p11);
            phi[ks][3] = pack_h2(p12, p13);
        }
        lsum0 = lsum0 * f0 + sum0;
        lsum1 = lsum1 * f1 + sum1;

#pragma unroll
        for (int ni = 0; ni < 8; ni++) {
            o[ni][0] *= f0; o[ni][1] *= f0;
            o[ni][2] *= f1; o[ni][3] *= f1;
        }

        // ---- O += Ph @ Vh ----
#pragma unroll
        for (int ks = 0; ks < 4; ks++) {
            uint32_t vh[4][4];
#pragma unroll
            for (int dg = 0; dg < 4; dg++)
                ldsm_x4_t(vh[dg], kvbase + KV_PLANE +
                                  (uint32_t)((Rv + ks * 16) * 128) +
                                  (uint32_t)((((cvb + 2 * dg) ^ xorV)) << 4));
#pragma unroll
            for (int ni = 0; ni < 8; ni++)
                mma16816(o[ni], phi[ks], &vh[ni >> 1][(ni & 1) * 2]);
        }
    }

    // ---- finalize ----
    lsum0 += __shfl_xor_sync(0xffffffffu, lsum0, 1);
    lsum0 += __shfl_xor_sync(0xffffffffu, lsum0, 2);
    lsum1 += __shfl_xor_sync(0xffffffffu, lsum1, 1);
    lsum1 += __shfl_xor_sync(0xffffffffu, lsum1, 2);
    const float inv0 = 1.f / lsum0;
    const float inv1 = 1.f / lsum1;

    const size_t orow0 = (rowbase + qr) * DIMN + h * HD;
    const size_t orow1 = (rowbase + qr + 8) * DIMN + h * HD;
#pragma unroll
    for (int ni = 0; ni < 8; ni++) {
        const int d = ni * 8 + c2;
        *(__half2*)(Ohi + orow0 + d) =
            __half2{__float2half_rn(o[ni][0] * inv0), __float2half_rn(o[ni][1] * inv0)};
        *(__half2*)(Ohi + orow1 + d) =
            __half2{__float2half_rn(o[ni][2] * inv1), __float2half_rn(o[ni][3] * inv1)};
    }
}

// ---------------------------------------------------------------------------
extern "C" void kernel_launch(void* const* d_in, const int* in_sizes, int n_in,
                              void* d_out, int out_size)
{
    const float* q  = (const float*)d_in[0];
    const float* Wq = (const float*)d_in[1];
    const float* Wk = (const float*)d_in[2];
    const float* Wv = (const float*)d_in[3];
    const float* pe = (const float*)d_in[4];
    const float* Wo = (const float*)d_in[5];
    const float* bo = (const float*)d_in[6];
    float* out = (float*)d_out;

    __half *QKVhi, *qhi, *Ohi, *Wch, *Woh;
    float* pe2;
    cudaGetSymbolAddress((void**)&QKVhi, g_QKVhi);
    cudaGetSymbolAddress((void**)&qhi, g_qhi);
    cudaGetSymbolAddress((void**)&Ohi, g_Ohi);
    cudaGetSymbolAddress((void**)&Wch, g_Wcat_hi);
    cudaGetSymbolAddress((void**)&Woh, g_Wo_hi);
    cudaGetSymbolAddress((void**)&pe2, g_pe2);

    const int nq = MROWS * DIMN;
    const int nw = DIMN * DIMN;
    const int np = SEQ * SEQ;

    tohalf_kernel<<<nq / 4 / 256, 256>>>(q, qhi, nq);
    tohalf_kernel<<<nw / 4 / 256, 256>>>(Wq, Wch, nw);
    tohalf_kernel<<<nw / 4 / 256, 256>>>(Wk, Wch + nw, nw);
    tohalf_kernel<<<nw / 4 / 256, 256>>>(Wv, Wch + 2 * nw, nw);
    tohalf_kernel<<<nw / 4 / 256, 256>>>(Wo, Woh, nw);
    scale_kernel<<<np / 4 / 256, 256>>>(pe, pe2, np);

    cudaFuncSetAttribute(gemm_f16x1<false, true>,
                         cudaFuncAttributeMaxDynamicSharedMemorySize, GEMM_SMEM);
    cudaFuncSetAttribute(gemm_f16x1<true, false>,
                         cudaFuncAttributeMaxDynamicSharedMemorySize, GEMM_SMEM);
    cudaFuncSetAttribute(attn_mma_kernel,
                         cudaFuncAttributeMaxDynamicSharedMemorySize, ATTN_SMEM);

    // Fused QKV projection -> fp16 hi [15360, 3072]
    gemm_f16x1<false, true><<<dim3(PLD / 128, MROWS / 128), 256, GEMM_SMEM>>>(
        qhi, Wch, nullptr, nullptr, QKVhi, PLD);

    // Tensor-core flash attention -> fp16 hi O
    attn_mma_kernel<<<dim3(SEQ / QROWS, BATCH * HEADS), ATHREADS, ATTN_SMEM>>>(
        pe2, QKVhi, Ohi);

    // Output projection + bias -> fp32 out
    gemm_f16x1<true, false><<<dim3(DIMN / 128, MROWS / 128), 256, GEMM_SMEM>>>(
        Ohi, Woh, bo, out, nullptr, DIMN);
}